// round 15
// baseline (speedup 1.0000x reference)
#include <cuda_runtime.h>
#include <math.h>

typedef unsigned long long u64;

#define D_DIM 3072
#define C_DIM 10
#define B_DIM 4096
#define BLOCKS 148
#define WARPS 14
#define THREADS 448
#define D_HALF 1536
#define NT 12                 // 1536 / 128 tiles per half
#define NPAIR 15360           // 3072 * 5 packed W pairs
#define XSTAGES 3

#define EPS_REG 0.1f
#define NUM_STAB 1e-6f

// smem byte offsets (dynamic)
#define SM_W 0
#define SM_X (NPAIR * 8)                         // 122880
#define SM_COMB (SM_X + XSTAGES * WARPS * 4 * 512)   // +86016 = 208896
#define SM_M55 (SM_COMB + WARPS * 20 * 8)            // +2240  = 211136
#define SM_WS (SM_M55 + 56 * 4)
#define SM_TOTAL (SM_WS + 16 * 4)

__device__ float g_M55[55];
__device__ float g_partials[BLOCKS];
__device__ unsigned g_Mdone = 0;
__device__ unsigned g_count = 0;

// ---- packed fp32x2 helpers ----
__device__ __forceinline__ u64 ffma2(u64 a, u64 b, u64 c) {
    u64 d; asm("fma.rn.f32x2 %0, %1, %2, %3;" : "=l"(d) : "l"(a), "l"(b), "l"(c));
    return d;
}
__device__ __forceinline__ u64 add2(u64 a, u64 b) {
    u64 d; asm("add.rn.f32x2 %0, %1, %2;" : "=l"(d) : "l"(a), "l"(b));
    return d;
}
__device__ __forceinline__ u64 pk2(float a, float b) {
    u64 r; asm("mov.b64 %0, {%1, %2};" : "=l"(r) : "f"(a), "f"(b));
    return r;
}
__device__ __forceinline__ void unpk(u64 v, float& lo, float& hi) {
    asm("mov.b64 {%0, %1}, %2;" : "=f"(lo), "=f"(hi) : "l"(v));
}
__device__ __forceinline__ u64 shfl64(u64 v, int m) {
    unsigned lo, hi;
    asm("mov.b64 {%0, %1}, %2;" : "=r"(lo), "=r"(hi) : "l"(v));
    lo = __shfl_xor_sync(0xffffffffu, lo, m);
    hi = __shfl_xor_sync(0xffffffffu, hi, m);
    u64 r; asm("mov.b64 %0, {%1, %2};" : "=l"(r) : "r"(lo), "r"(hi));
    return r;
}

// ---- cp.async helpers ----
__device__ __forceinline__ void cp_async16(unsigned dst, const float* src) {
    asm volatile("cp.async.cg.shared.global [%0], [%1], 16;"
                 :: "r"(dst), "l"(src) : "memory");
}
__device__ __forceinline__ void cp_commit() {
    asm volatile("cp.async.commit_group;" ::: "memory");
}
template<int N> __device__ __forceinline__ void cp_wait() {
    asm volatile("cp.async.wait_group %0;" :: "n"(N) : "memory");
}

// ---- L2-scoped helpers (no threadfence -> no L1 flush) ----
__device__ __forceinline__ void st_cg_f(float* p, float v) {
    asm volatile("st.cg.f32 [%0], %1;" :: "l"(p), "f"(v) : "memory");
}
__device__ __forceinline__ float ld_cg_f(const float* p) {
    float v; asm volatile("ld.cg.f32 %0, [%1];" : "=f"(v) : "l"(p) : "memory");
    return v;
}
__device__ __forceinline__ void st_cg_u32(unsigned* p, unsigned v) {
    asm volatile("st.cg.u32 [%0], %1;" :: "l"(p), "r"(v) : "memory");
}
__device__ __forceinline__ unsigned atom_add_acqrel(unsigned* p, unsigned v) {
    unsigned old;
    asm volatile("atom.acq_rel.gpu.add.u32 %0, [%1], %2;"
                 : "=r"(old) : "l"(p), "r"(v) : "memory");
    return old;
}
__device__ __forceinline__ unsigned atom_add_release(unsigned* p, unsigned v) {
    unsigned old;
    asm volatile("atom.release.gpu.add.u32 %0, [%1], %2;"
                 : "=r"(old) : "l"(p), "r"(v) : "memory");
    return old;
}
__device__ __forceinline__ unsigned ld_acquire(const unsigned* p) {
    unsigned v;
    asm volatile("ld.acquire.gpu.u32 %0, [%1];" : "=r"(v) : "l"(p) : "memory");
    return v;
}

// upper-triangle index into M (i<=j): i*10 - i(i+1)/2 + j
__device__ __forceinline__ float Mget(const float* sM, int a, int b) {
    int i = (a < b) ? a : b;
    int j = (a < b) ? b : a;
    return sM[i * 10 - (i * (i + 1)) / 2 + j];
}

extern __shared__ unsigned char smem_raw[];

__global__ __launch_bounds__(THREADS, 1)
void jac_kernel(const float* __restrict__ data,
                const float* __restrict__ W,
                float* __restrict__ out) {
    u64*   sW2   = (u64*)(smem_raw + SM_W);       // [5][3072] permuted packed W
    float* sXf   = (float*)(smem_raw + SM_X);     // x ring [3][14][4][128]
    u64*   sComb = (u64*)(smem_raw + SM_COMB);    // [14][4][5] warp partials
    float* sM55  = (float*)(smem_raw + SM_M55);   // 55
    float* sWs   = (float*)(smem_raw + SM_WS);    // 14 warp partials
    __shared__ bool sLast;

    unsigned sX_u32;   // shared-space u32 address of sXf
    {
        unsigned r;
        asm("{ .reg .u64 t; cvta.to.shared.u64 t, %1; cvt.u32.u64 %0, t; }"
            : "=r"(r) : "l"(sXf));
        sX_u32 = r;
    }

    const int tid  = threadIdx.x;
    const int w    = tid >> 5;
    const int lane = tid & 31;
    const int half = (w >= 7) ? 1 : 0;
    const int wsub = w - 7 * half;
    const int b    = blockIdx.x;
    const int nrb     = (b < 100) ? 28 : 27;
    const int rowbase = (b < 100) ? 28 * b : 2800 + 27 * (b - 100);

    // ---- stage W into smem, j-packed + d-permuted (conflict-free reads) ----
    for (int i = tid; i < NPAIR; i += THREADS) {
        int d  = i / 5;
        int jp = i - d * 5;
        float2 t = *reinterpret_cast<const float2*>(W + (size_t)d * C_DIM + 2 * jp);
        sW2[(size_t)jp * D_DIM + (d & 3) * 768 + (d >> 2)] = pk2(t.x, t.y);
    }

    // ---- blocks 0..54: warp 0 computes one upper-tri M entry, publishes ----
    if (b < 55 && w == 0) {
        int i = 0, rem = b;
        while (rem >= C_DIM - i) { rem -= C_DIM - i; i++; }
        const int j = i + rem;
        float s = 0.f;
        #pragma unroll 8
        for (int d = lane; d < D_DIM; d += 32)
            s = fmaf(W[(size_t)d * C_DIM + i], W[(size_t)d * C_DIM + j], s);
        #pragma unroll
        for (int off = 16; off; off >>= 1)
            s += __shfl_xor_sync(0xffffffffu, s, off);
        if (lane == 0) {
            st_cg_f(&g_M55[b], s);
            atom_add_release(&g_Mdone, 1u);
        }
    }
    __syncthreads();

    // ---- row assignment: warp covers 4 rows x one D-half ----
    const int r0 = rowbase + wsub * 4;
    const int nr = min(4, nrb - wsub * 4);
    const float* xp[4];
    #pragma unroll
    for (int r = 0; r < 4; r++) {
        int rr = r0 + ((r < nr) ? r : nr - 1);
        xp[r] = data + (size_t)rr * D_DIM + half * D_HALF + lane * 4;
    }

    // per-lane x ring addresses: stage s, slot (w,r): 512B per slot
    // byte offset = ((s*14 + w)*4 + r)*512 + lane*16
    const unsigned myX = sX_u32 + (unsigned)(w * 4) * 512 + (unsigned)lane * 16;

    u64 acc[4][5];
    #pragma unroll
    for (int r = 0; r < 4; r++)
        #pragma unroll
        for (int jp = 0; jp < 5; jp++) acc[r][jp] = 0ULL;

    // ---- prologue: fill 3 stages ----
    #pragma unroll
    for (int s = 0; s < XSTAGES; s++) {
        #pragma unroll
        for (int r = 0; r < 4; r++)
            cp_async16(myX + (unsigned)(s * WARPS * 4 + r) * 512, xp[r] + s * 128);
        cp_commit();
    }

    const u64* wl = sW2 + half * 384 + lane;
    const float* sXl = sXf + (size_t)(w * 4) * 128 + lane * 4;

    // ---- mainloop: fully unrolled 12 tiles ----
    #pragma unroll
    for (int t = 0; t < NT; t++) {
        if (t < NT - 2)      cp_wait<2>();
        else if (t == NT - 2) cp_wait<1>();
        else                 cp_wait<0>();

        const int st = t % XSTAGES;
        float4 xv[4];
        #pragma unroll
        for (int r = 0; r < 4; r++)
            xv[r] = *reinterpret_cast<const float4*>(
                sXl + (size_t)(st * WARPS * 4 + r) * 128);

        if (t + XSTAGES < NT) {     // refill this stage with tile t+3
            #pragma unroll
            for (int r = 0; r < 4; r++)
                cp_async16(myX + (unsigned)(st * WARPS * 4 + r) * 512,
                           xp[r] + (t + XSTAGES) * 128);
            cp_commit();
        }

        const u64* wt = wl + t * 32;
        #pragma unroll
        for (int c = 0; c < 4; c++) {
            u64 wv[5];
            #pragma unroll
            for (int jp = 0; jp < 5; jp++)
                wv[jp] = wt[(size_t)jp * D_DIM + c * 768];     // conflict-free
            #pragma unroll
            for (int r = 0; r < 4; r++) {
                const float xc = (c == 0) ? xv[r].x : (c == 1) ? xv[r].y
                               : (c == 2) ? xv[r].z : xv[r].w;
                const u64 xx = pk2(xc, xc);
                #pragma unroll
                for (int jp = 0; jp < 5; jp++)
                    acc[r][jp] = ffma2(xx, wv[jp], acc[r][jp]);
            }
        }
    }

    // ---- packed butterfly reduce; lane 0 stores warp partials ----
    #pragma unroll
    for (int r = 0; r < 4; r++)
        #pragma unroll
        for (int jp = 0; jp < 5; jp++) {
            u64 v = acc[r][jp];
            v = add2(v, shfl64(v, 16));
            v = add2(v, shfl64(v, 8));
            v = add2(v, shfl64(v, 4));
            v = add2(v, shfl64(v, 2));
            v = add2(v, shfl64(v, 1));
            acc[r][jp] = v;
        }
    if (lane == 0) {
        #pragma unroll
        for (int r = 0; r < 4; r++)
            #pragma unroll
            for (int jp = 0; jp < 5; jp++)
                sComb[(w * 4 + r) * 5 + jp] = acc[r][jp];
    }

    // ---- wait for M ----
    __syncthreads();
    if (tid == 0) {
        unsigned v = ld_acquire(&g_Mdone);
        while (v < 55) { __nanosleep(32); v = ld_acquire(&g_Mdone); }
    }
    __syncthreads();
    if (tid < 55) sM55[tid] = ld_cg_f(&g_M55[tid]);
    __syncthreads();

    // ---- analytic epilogue: warps 0..6, lane r (< nr) handles row r0+r ----
    float reg = 0.f;
    if (half == 0 && lane < nr) {
        const float ALPHA = 1.0f - (float)C_DIM * NUM_STAB;
        float z[C_DIM];
        #pragma unroll
        for (int jp = 0; jp < 5; jp++) {
            u64 v = add2(sComb[(w * 4 + lane) * 5 + jp],
                         sComb[((w + 7) * 4 + lane) * 5 + jp]);
            unpk(v, z[2 * jp], z[2 * jp + 1]);
        }

        float zmax = z[0];
        #pragma unroll
        for (int j = 1; j < C_DIM; j++) zmax = fmaxf(zmax, z[j]);

        float e[C_DIM], S = 0.f;
        #pragma unroll
        for (int j = 0; j < C_DIM; j++) { e[j] = expf(z[j] - zmax); S += e[j]; }
        const float invS = 1.f / S;

        float sig[C_DIM], p[C_DIM], s[C_DIM];
        float ssum = 0.f, psum_m = 0.f;
        #pragma unroll
        for (int j = 0; j < C_DIM; j++) {
            sig[j] = e[j] * invS;
            p[j]   = fmaf(ALPHA, sig[j], NUM_STAB);
            s[j]   = sqrtf(p[j]);
            ssum  += s[j];
            if (j < C_DIM - 1) psum_m += p[j];
        }
        const float sL = s[C_DIM - 1];
        const float t  = 1.f / (1.f - sL);

        float arg = ssum * 0.31622776601683794f;       // 1/sqrt(10)
        arg = fminf(1.f, fmaxf(-1.f, arg));
        const float delta = 2.f * acosf(arg);
        const float rho   = (2.f * (1.f - sL) - psum_m) * t;

        float v[C_DIM], qq = 0.f;
        #pragma unroll
        for (int k = 0; k < C_DIM; k++) {
            float a = 0.f;
            #pragma unroll
            for (int j = 0; j < C_DIM; j++)
                a = fmaf(Mget(sM55, k, j), sig[j], a);
            v[k] = a;
            qq = fmaf(sig[k], a, qq);
        }

        const float gL = ALPHA * sig[C_DIM - 1] / sL;
        float fro = 0.f;
        #pragma unroll
        for (int i = 0; i < C_DIM - 1; i++) {
            float a  = t * ALPHA * sig[i] / s[i];
            float bb = s[i] * t * t * gL;
            float c  = a + bb;
            fro += a * a * Mget(sM55, i, i)
                 + bb * bb * Mget(sM55, 9, 9)
                 + c * c * qq
                 + 2.f * a * bb * Mget(sM55, i, 9)
                 - 2.f * c * (a * v[i] + bb * v[C_DIM - 1]);
        }
        const float jac_norm = sqrtf(fmaxf(fro, 0.f));
        const float xv = jac_norm - delta / (rho * EPS_REG);
        reg = (xv > 0.f) ? xv : (expf(xv) - 1.f);
    }

    // ---- deterministic block reduction ----
    #pragma unroll
    for (int off = 16; off; off >>= 1)
        reg += __shfl_xor_sync(0xffffffffu, reg, off);
    if (lane == 0) sWs[w] = reg;
    __syncthreads();
    if (tid == 0) {
        float ssum = 0.f;
        #pragma unroll
        for (int k = 0; k < WARPS; k++) ssum += sWs[k];
        st_cg_f(&g_partials[b], ssum);
        sLast = (atom_add_acqrel(&g_count, 1u) == BLOCKS - 1);
    }
    __syncthreads();

    // ---- last block: fixed-order final reduction over 148 partials ----
    if (sLast) {
        float v = (tid < BLOCKS) ? ld_cg_f(&g_partials[tid]) : 0.f;
        #pragma unroll
        for (int off = 16; off; off >>= 1)
            v += __shfl_xor_sync(0xffffffffu, v, off);
        if (lane == 0) sWs[w] = v;
        __syncthreads();
        if (tid == 0) {
            float ssum = 0.f;
            #pragma unroll
            for (int k = 0; k < WARPS; k++) ssum += sWs[k];
            out[0] = ssum * (1.0f / (float)B_DIM);
            st_cg_u32(&g_count, 0u);
            st_cg_u32(&g_Mdone, 0u);
        }
    }
}

extern "C" void kernel_launch(void* const* d_in, const int* in_sizes, int n_in,
                              void* d_out, int out_size) {
    const float* data = (const float*)d_in[0];   // [4096, 3072] f32
    const float* W    = (const float*)d_in[1];   // [3072, 10]   f32
    float* out        = (float*)d_out;           // scalar f32

    cudaFuncSetAttribute(jac_kernel, cudaFuncAttributeMaxDynamicSharedMemorySize,
                         SM_TOTAL);
    jac_kernel<<<BLOCKS, THREADS, SM_TOTAL>>>(data, W, out);
}

// round 16
// speedup vs baseline: 1.2947x; 1.2947x over previous
#include <cuda_runtime.h>
#include <math.h>

typedef unsigned long long u64;

#define D_DIM 3072
#define C_DIM 10
#define B_DIM 4096
#define BLOCKS 128
#define WARPS 8
#define THREADS 256
#define D_HALF 1536
#define NT 12                 // 1536 / 128 tiles per half
#define RW 8                  // rows per warp
#define NPAIR 15360           // 3072 * 5 packed W pairs

#define EPS_REG 0.1f
#define NUM_STAB 1e-6f

__device__ float g_M55[55];
__device__ float g_partials[BLOCKS];
__device__ unsigned g_Mdone = 0;
__device__ unsigned g_count = 0;

// ---- packed fp32x2 helpers ----
__device__ __forceinline__ u64 ffma2(u64 a, u64 b, u64 c) {
    u64 d; asm("fma.rn.f32x2 %0, %1, %2, %3;" : "=l"(d) : "l"(a), "l"(b), "l"(c));
    return d;
}
__device__ __forceinline__ u64 add2(u64 a, u64 b) {
    u64 d; asm("add.rn.f32x2 %0, %1, %2;" : "=l"(d) : "l"(a), "l"(b));
    return d;
}
__device__ __forceinline__ u64 pk2(float a, float b) {
    u64 r; asm("mov.b64 %0, {%1, %2};" : "=l"(r) : "f"(a), "f"(b));
    return r;
}
__device__ __forceinline__ void unpk(u64 v, float& lo, float& hi) {
    asm("mov.b64 {%0, %1}, %2;" : "=f"(lo), "=f"(hi) : "l"(v));
}
__device__ __forceinline__ u64 shfl64(u64 v, int m) {
    unsigned lo, hi;
    asm("mov.b64 {%0, %1}, %2;" : "=r"(lo), "=r"(hi) : "l"(v));
    lo = __shfl_xor_sync(0xffffffffu, lo, m);
    hi = __shfl_xor_sync(0xffffffffu, hi, m);
    u64 r; asm("mov.b64 %0, {%1, %2};" : "=l"(r) : "r"(lo), "r"(hi));
    return r;
}

// ---- L2-scoped helpers (no threadfence -> no L1 flush) ----
__device__ __forceinline__ void st_cg_f(float* p, float v) {
    asm volatile("st.cg.f32 [%0], %1;" :: "l"(p), "f"(v) : "memory");
}
__device__ __forceinline__ float ld_cg_f(const float* p) {
    float v; asm volatile("ld.cg.f32 %0, [%1];" : "=f"(v) : "l"(p) : "memory");
    return v;
}
__device__ __forceinline__ void st_cg_u32(unsigned* p, unsigned v) {
    asm volatile("st.cg.u32 [%0], %1;" :: "l"(p), "r"(v) : "memory");
}
__device__ __forceinline__ unsigned atom_add_acqrel(unsigned* p, unsigned v) {
    unsigned old;
    asm volatile("atom.acq_rel.gpu.add.u32 %0, [%1], %2;"
                 : "=r"(old) : "l"(p), "r"(v) : "memory");
    return old;
}
__device__ __forceinline__ unsigned atom_add_release(unsigned* p, unsigned v) {
    unsigned old;
    asm volatile("atom.release.gpu.add.u32 %0, [%1], %2;"
                 : "=r"(old) : "l"(p), "r"(v) : "memory");
    return old;
}
__device__ __forceinline__ unsigned ld_acquire(const unsigned* p) {
    unsigned v;
    asm volatile("ld.acquire.gpu.u32 %0, [%1];" : "=r"(v) : "l"(p) : "memory");
    return v;
}

// upper-triangle index into M (i<=j): i*10 - i(i+1)/2 + j
__device__ __forceinline__ float Mget(const float* sM, int a, int b) {
    int i = (a < b) ? a : b;
    int j = (a < b) ? b : a;
    return sM[i * 10 - (i * (i + 1)) / 2 + j];
}

extern __shared__ unsigned char smem_raw[];

__global__ __launch_bounds__(THREADS, 1)
void jac_kernel(const float* __restrict__ data,
                const float* __restrict__ W,
                float* __restrict__ out) {
    u64*   sW2   = (u64*)smem_raw;                 // [5][3072] permuted packed W
    u64*   sComb = sW2 + NPAIR;                    // [8 warps][8 rows][5]
    float* sM55  = (float*)(sComb + WARPS * RW * 5);
    float* sWs   = sM55 + 56;                      // 8 warp partials
    __shared__ bool sLast;

    const int tid  = threadIdx.x;
    const int w    = tid >> 5;
    const int lane = tid & 31;
    const int rg   = w >> 1;          // row group 0..3 (8 rows each)
    const int half = w & 1;           // D half
    const int b    = blockIdx.x;

    // ---- stage W into smem, j-packed + d-permuted (no integer division) ----
    for (int d = tid; d < D_DIM; d += THREADS) {
        const float2* wr = reinterpret_cast<const float2*>(W + (size_t)d * C_DIM);
        const int dst = (d & 3) * 768 + (d >> 2);
        #pragma unroll
        for (int jp = 0; jp < 5; jp++) {
            float2 t = wr[jp];
            sW2[(size_t)jp * D_DIM + dst] = pk2(t.x, t.y);
        }
    }

    // ---- blocks 0..54: warp 0 computes one upper-tri M entry, publishes ----
    if (b < 55 && w == 0) {
        int i = 0, rem = b;
        while (rem >= C_DIM - i) { rem -= C_DIM - i; i++; }
        const int j = i + rem;
        float s = 0.f;
        #pragma unroll 8
        for (int d = lane; d < D_DIM; d += 32)
            s = fmaf(W[(size_t)d * C_DIM + i], W[(size_t)d * C_DIM + j], s);
        #pragma unroll
        for (int off = 16; off; off >>= 1)
            s += __shfl_xor_sync(0xffffffffu, s, off);
        if (lane == 0) {
            st_cg_f(&g_M55[b], s);
            atom_add_release(&g_Mdone, 1u);
        }
    }
    __syncthreads();

    // ---- row assignment: warp covers 8 rows x one D-half (exact fit) ----
    const int r0 = b * 32 + rg * RW;
    const float* xbase = data + (size_t)r0 * D_DIM + half * D_HALF + lane * 4;

    u64 acc[RW][5];
    #pragma unroll
    for (int r = 0; r < RW; r++)
        #pragma unroll
        for (int jp = 0; jp < 5; jp++) acc[r][jp] = 0ULL;

    // 3-deep x prefetch: 24 LDG.128 in flight per warp
    float4 xb[3][RW];
    #pragma unroll
    for (int s = 0; s < 3; s++)
        #pragma unroll
        for (int r = 0; r < RW; r++)
            xb[s][r] = *reinterpret_cast<const float4*>(
                xbase + (size_t)r * D_DIM + s * 128);

    const u64* wl = sW2 + half * 384 + lane;

    #pragma unroll
    for (int t = 0; t < NT; t++) {
        const int st = t % 3;
        float4 xv[RW];
        #pragma unroll
        for (int r = 0; r < RW; r++) xv[r] = xb[st][r];
        if (t + 3 < NT) {
            #pragma unroll
            for (int r = 0; r < RW; r++)
                xb[st][r] = *reinterpret_cast<const float4*>(
                    xbase + (size_t)r * D_DIM + (t + 3) * 128);
        }
        const u64* wt = wl + t * 32;
        #pragma unroll
        for (int c = 0; c < 4; c++) {
            u64 wv[5];
            #pragma unroll
            for (int jp = 0; jp < 5; jp++)
                wv[jp] = wt[(size_t)jp * D_DIM + c * 768];     // conflict-free
            #pragma unroll
            for (int r = 0; r < RW; r++) {
                const float xc = (c == 0) ? xv[r].x : (c == 1) ? xv[r].y
                               : (c == 2) ? xv[r].z : xv[r].w;
                const u64 xx = pk2(xc, xc);
                #pragma unroll
                for (int jp = 0; jp < 5; jp++)
                    acc[r][jp] = ffma2(xx, wv[jp], acc[r][jp]);   // 40 FFMA2 per LDS group
            }
        }
    }

    // ---- packed butterfly reduce; lane 0 stores warp partials ----
    #pragma unroll
    for (int r = 0; r < RW; r++)
        #pragma unroll
        for (int jp = 0; jp < 5; jp++) {
            u64 v = acc[r][jp];
            v = add2(v, shfl64(v, 16));
            v = add2(v, shfl64(v, 8));
            v = add2(v, shfl64(v, 4));
            v = add2(v, shfl64(v, 2));
            v = add2(v, shfl64(v, 1));
            acc[r][jp] = v;
        }
    if (lane == 0) {
        #pragma unroll
        for (int r = 0; r < RW; r++)
            #pragma unroll
            for (int jp = 0; jp < 5; jp++)
                sComb[(w * RW + r) * 5 + jp] = acc[r][jp];
    }

    // ---- wait for M ----
    __syncthreads();
    if (tid == 0) {
        unsigned v = ld_acquire(&g_Mdone);
        while (v < 55) { __nanosleep(32); v = ld_acquire(&g_Mdone); }
    }
    __syncthreads();
    if (tid < 55) sM55[tid] = ld_cg_f(&g_M55[tid]);
    __syncthreads();

    // ---- analytic epilogue: warp 0, lane handles row b*32 + lane ----
    float reg = 0.f;
    if (w == 0) {
        const int lrg = lane >> 3;         // row group of this row
        const int lr  = lane & 7;          // row within group
        const float ALPHA = 1.0f - (float)C_DIM * NUM_STAB;
        float z[C_DIM];
        #pragma unroll
        for (int jp = 0; jp < 5; jp++) {
            u64 v = add2(sComb[((lrg * 2 + 0) * RW + lr) * 5 + jp],
                         sComb[((lrg * 2 + 1) * RW + lr) * 5 + jp]);
            unpk(v, z[2 * jp], z[2 * jp + 1]);
        }

        float zmax = z[0];
        #pragma unroll
        for (int j = 1; j < C_DIM; j++) zmax = fmaxf(zmax, z[j]);

        float e[C_DIM], S = 0.f;
        #pragma unroll
        for (int j = 0; j < C_DIM; j++) { e[j] = expf(z[j] - zmax); S += e[j]; }
        const float invS = 1.f / S;

        float sig[C_DIM], p[C_DIM], s[C_DIM];
        float ssum = 0.f, psum_m = 0.f;
        #pragma unroll
        for (int j = 0; j < C_DIM; j++) {
            sig[j] = e[j] * invS;
            p[j]   = fmaf(ALPHA, sig[j], NUM_STAB);
            s[j]   = sqrtf(p[j]);
            ssum  += s[j];
            if (j < C_DIM - 1) psum_m += p[j];
        }
        const float sL = s[C_DIM - 1];
        const float t  = 1.f / (1.f - sL);

        float arg = ssum * 0.31622776601683794f;       // 1/sqrt(10)
        arg = fminf(1.f, fmaxf(-1.f, arg));
        const float delta = 2.f * acosf(arg);
        const float rho   = (2.f * (1.f - sL) - psum_m) * t;

        float v[C_DIM], qq = 0.f;
        #pragma unroll
        for (int k = 0; k < C_DIM; k++) {
            float a = 0.f;
            #pragma unroll
            for (int j = 0; j < C_DIM; j++)
                a = fmaf(Mget(sM55, k, j), sig[j], a);
            v[k] = a;
            qq = fmaf(sig[k], a, qq);
        }

        const float gL = ALPHA * sig[C_DIM - 1] / sL;
        float fro = 0.f;
        #pragma unroll
        for (int i = 0; i < C_DIM - 1; i++) {
            float a  = t * ALPHA * sig[i] / s[i];
            float bb = s[i] * t * t * gL;
            float c  = a + bb;
            fro += a * a * Mget(sM55, i, i)
                 + bb * bb * Mget(sM55, 9, 9)
                 + c * c * qq
                 + 2.f * a * bb * Mget(sM55, i, 9)
                 - 2.f * c * (a * v[i] + bb * v[C_DIM - 1]);
        }
        const float jac_norm = sqrtf(fmaxf(fro, 0.f));
        const float xv = jac_norm - delta / (rho * EPS_REG);
        reg = (xv > 0.f) ? xv : (expf(xv) - 1.f);

        // warp 0 holds all 32 rows: butterfly then publish
        #pragma unroll
        for (int off = 16; off; off >>= 1)
            reg += __shfl_xor_sync(0xffffffffu, reg, off);
        if (lane == 0) {
            st_cg_f(&g_partials[b], reg);
            sLast = (atom_add_acqrel(&g_count, 1u) == BLOCKS - 1);
        }
    }
    __syncthreads();

    // ---- last block: fixed-order final reduction over 128 partials ----
    if (sLast) {
        float v = (tid < BLOCKS) ? ld_cg_f(&g_partials[tid]) : 0.f;
        #pragma unroll
        for (int off = 16; off; off >>= 1)
            v += __shfl_xor_sync(0xffffffffu, v, off);
        if (lane == 0) sWs[w] = v;
        __syncthreads();
        if (tid == 0) {
            float ssum = 0.f;
            #pragma unroll
            for (int k = 0; k < WARPS; k++) ssum += sWs[k];
            out[0] = ssum * (1.0f / (float)B_DIM);
            st_cg_u32(&g_count, 0u);
            st_cg_u32(&g_Mdone, 0u);
        }
    }
}

extern "C" void kernel_launch(void* const* d_in, const int* in_sizes, int n_in,
                              void* d_out, int out_size) {
    const float* data = (const float*)d_in[0];   // [4096, 3072] f32
    const float* W    = (const float*)d_in[1];   // [3072, 10]   f32
    float* out        = (float*)d_out;           // scalar f32

    const int smemBytes = NPAIR * 8 + WARPS * RW * 5 * 8 + 80 * 4;  // ~126.4 KB
    cudaFuncSetAttribute(jac_kernel, cudaFuncAttributeMaxDynamicSharedMemorySize,
                         smemBytes);
    jac_kernel<<<BLOCKS, THREADS, smemBytes>>>(data, W, out);
}